// round 15
// baseline (speedup 1.0000x reference)
#include <cuda_runtime.h>
#include <cstdint>

#define AN 13824          // 24*24*24 anchors
#define NT 512            // threads per CTA
#define HALF 6912         // anchors per scan-CTA
#define HV 1728           // float4s per half
#define TK 60             // TOPK
#define NMSK 20           // NMS_TOPK
#define SEGSZ 32          // per-warp segment capacity (mean 5.3, sigma 2.3 -> 11 sigma)
#define NWARP 16
#define CAPL 512          // local candidate capacity
#define NB 256            // batches
#define THRF 2.25f        // fast-path threshold: ~169+-13 per batch, ~84.5+-9 per half

__device__ unsigned long long g_top[NB][2][NMSK];
__device__ int g_c[NB][2];       // local qualifier count (-1 on overflow)
__device__ int g_ticket[NB];     // zero-init; finisher resets

__device__ __forceinline__ unsigned int fkey(float x) {
    unsigned int b = __float_as_uint(x);
    return (b & 0x80000000u) ? ~b : (b | 0x80000000u);
}
__device__ __forceinline__ float fkey_inv(unsigned int u) {
    unsigned int b = (u & 0x80000000u) ? (u & 0x7fffffffu) : ~u;
    return __uint_as_float(b);
}

__global__ __launch_bounds__(NT, 3)
void detect_split_kernel(const float* __restrict__ cls,
                         const float* __restrict__ shp,
                         const float* __restrict__ off,
                         float* __restrict__ out)
{
    const int blk  = blockIdx.x;
    const int b    = blk >> 1;
    const int h    = blk & 1;
    const int t    = threadIdx.x;
    const int lane = t & 31;
    const int wid  = t >> 5;
    const unsigned int ltmask = (1u << lane) - 1u;

    __shared__ unsigned long long s_seg[NWARP][SEGSZ];
    __shared__ unsigned long long s_cand[CAPL];
    __shared__ int   s_segcnt[NWARP], s_segoff[NWARP];
    __shared__ int   s_tot, s_maxseg;
    __shared__ unsigned long long s_key[TK];
    __shared__ float s_sc[NMSK];
    __shared__ int   s_red[NWARP];
    __shared__ int   s_n2;
    __shared__ float s_gv[6][NMSK];
    __shared__ float s_ctr[NMSK][3], s_sz[NMSK][3];
    __shared__ float s_lo[NMSK][3], s_hi[NMSK][3], s_vol[NMSK];
    __shared__ unsigned int s_m[NMSK];
    __shared__ unsigned int s_kept;
    __shared__ int   s_fast;

    // ================= SCAN: this CTA's half-batch =================
    const float4* cb4 = (const float4*)(cls + (size_t)b * AN) + h * HV;
    const int i3  = t + NT * 3;
    const int i3c = (i3 < HV) ? i3 : (HV - 1);
    float4 v0 = __ldg(&cb4[t + NT * 0]);
    float4 v1 = __ldg(&cb4[t + NT * 1]);
    float4 v2 = __ldg(&cb4[t + NT * 2]);
    float4 v3 = __ldg(&cb4[i3c]);
    if (i3 >= HV) { v3.x = v3.y = v3.z = v3.w = -1e30f; }

    const int abase = h * HALF;   // anchor index offset of this half
    int wcnt = 0;
#define PUSHC(val, idx) \
    { unsigned int mm = __ballot_sync(0xffffffffu, (val) >= THRF); \
      if (mm) { \
        if ((val) >= THRF) { \
            int pos = wcnt + __popc(mm & ltmask); \
            if (pos < SEGSZ) \
                s_seg[wid][pos] = ((unsigned long long)fkey(val) << 14) | \
                                  (unsigned long long)(16383 - (idx)); \
        } \
        wcnt += __popc(mm); \
      } }
#define PUSH4(v, i) \
    PUSHC((v).x, abase + 4*(i) + 0); PUSHC((v).y, abase + 4*(i) + 1); \
    PUSHC((v).z, abase + 4*(i) + 2); PUSHC((v).w, abase + 4*(i) + 3);

    PUSH4(v0, t + NT * 0);
    PUSH4(v1, t + NT * 1);
    PUSH4(v2, t + NT * 2);
    PUSH4(v3, i3);
#undef PUSH4
#undef PUSHC

    if (lane == 0) s_segcnt[wid] = wcnt;
    __syncthreads();

    if (wid == 0) {
        int cnt = (lane < NWARP) ? s_segcnt[lane] : 0;
        int incl = cnt;
#pragma unroll
        for (int o = 1; o < 16; o <<= 1) {
            int v = __shfl_up_sync(0xffffffffu, incl, o);
            if (lane >= o) incl += v;
        }
        if (lane < NWARP) s_segoff[lane] = incl - cnt;
        int mx = __reduce_max_sync(0xffffffffu, (lane < NWARP) ? cnt : 0);
        int tt = __shfl_sync(0xffffffffu, incl, NWARP - 1);
        if (lane == 0) { s_tot = tt; s_maxseg = mx; }
    }
    __syncthreads();

    const int tot = s_tot;
    const bool ok = (tot >= NMSK) && (tot <= CAPL) && (s_maxseg <= SEGSZ);

    if (ok) {
        // compact, local top-20 rank
        {
            int n = (wcnt < SEGSZ) ? wcnt : SEGSZ;
            int base = s_segoff[wid];
            for (int p = lane; p < n; p += 32)
                s_cand[base + p] = s_seg[wid][p];
        }
        __syncthreads();
        for (int c = t; c < tot; c += NT) {
            unsigned long long k = s_cand[c];
            int r = 0;
#pragma unroll 4
            for (int m = 0; m < tot; m++)
                r += (s_cand[m] > k);
            if (r < NMSK) g_top[b][h][r] = k;
        }
    }
    if (t == 0) g_c[b][h] = ok ? tot : -1;
    __threadfence();
    __syncthreads();

    // ================= TICKET: second finisher runs the tail =================
    __shared__ int s_tick;
    if (t == 0) s_tick = atomicAdd(&g_ticket[b], 1);
    __syncthreads();
    if (s_tick != 1) return;
    if (t == 0) g_ticket[b] = 0;       // reset for next graph replay
    __threadfence();

    // ---------------- merge two local top-20s (or exact fallback) ----------------
    int cA = g_c[b][0], cB = g_c[b][1];
    if (t == 0) s_fast = (cA >= NMSK) && (cB >= NMSK) && (cA + cB >= TK);
    __syncthreads();

    if (s_fast) {
        // fast path: all top-60 scores sigmoid(>=2.25) > 0.15 -> cand = top-20 of union
        if (t < 2 * NMSK)
            s_cand[t] = g_top[b][t / NMSK][t % NMSK];
        __syncthreads();
        if (t < 2 * NMSK) {
            unsigned long long k = s_cand[t];
            int r = 0;
#pragma unroll
            for (int m = 0; m < 2 * NMSK; m++)
                r += (s_cand[m] > k);
            if (r < NMSK) s_key[r] = k;
        }
        __syncthreads();
    } else {
        // exact fallback (never taken for N(0,1) data): 50-bit key binary descent
        const float* cb = cls + (size_t)b * AN;
        unsigned long long cutk = 0;
        for (int bit = 49; bit >= 0; bit--) {
            unsigned long long c2 = cutk | (1ull << bit);
            int cc = 0;
            for (int i = t; i < AN; i += NT) {
                unsigned long long k = ((unsigned long long)fkey(__ldg(&cb[i])) << 14) |
                                       (unsigned long long)(16383 - i);
                cc += (k >= c2);
            }
            unsigned int ws = __reduce_add_sync(0xffffffffu, (unsigned int)cc);
            if (lane == 0) s_red[wid] = (int)ws;
            __syncthreads();
            int tt = 0;
#pragma unroll
            for (int w = 0; w < NWARP; w++)
                tt += s_red[w];
            if (tt >= TK) cutk = c2;
            __syncthreads();
        }
        // exactly TK unique keys >= cutk
        if (t == 0) s_n2 = 0;
        __syncthreads();
        for (int i = t; i < AN; i += NT) {
            unsigned long long k = ((unsigned long long)fkey(__ldg(&cb[i])) << 14) |
                                   (unsigned long long)(16383 - i);
            if (k >= cutk) {
                int p = atomicAdd(&s_n2, 1);
                if (p < TK) s_cand[p] = k;
            }
        }
        __syncthreads();
        // rank the 60, general validity -> cand rows
        for (int c = t; c < TK; c += NT) {
            unsigned long long k = s_cand[c];
            int r = 0;
            for (int m = 0; m < TK; m++)
                r += (s_cand[m] > k);
            s_key[r] = k;
        }
        __syncthreads();
        // general path: valid = score > 0.15, cand = first 20 valid; remap into s_key[0..19]
        __shared__ unsigned int sv[2];
        float sc0 = 0.0f;
        if (t < TK) {
            float logit = fkey_inv((unsigned int)(s_key[t] >> 14));
            sc0 = 1.0f / (1.0f + expf(-logit));
        }
        unsigned int vb = __ballot_sync(0xffffffffu, (t < TK) && (sc0 > 0.15f));
        if (wid < 2 && lane == 0) sv[wid] = vb;
        __syncthreads();
        unsigned long long valid = ((unsigned long long)sv[1] << 32) | sv[0];
        __shared__ unsigned long long s_k2[NMSK];
        __shared__ int s_nc2;
        if (t == 0) {
            int nc2 = __popcll(valid);
            s_nc2 = (nc2 > NMSK) ? NMSK : nc2;
        }
        if (t < TK && ((valid >> t) & 1ull)) {
            int rv = __popcll(valid & ((1ull << t) - 1ull));
            if (rv < NMSK) s_k2[rv] = s_key[t];
        }
        __syncthreads();
        if (t < NMSK) s_key[t] = (t < s_nc2) ? s_k2[t] : 0ull;
        __syncthreads();
        // pad: treat nc below via s_nc2 - store in s_fast slot trick
        if (t == 0) s_fast = -s_nc2;   // negative encodes fallback nc
        __syncthreads();
    }

    const int nc = s_fast ? ((s_fast > 0) ? NMSK : -s_fast) : NMSK;

    // scores for cand rows
    if (t < nc) {
        float logit = fkey_inv((unsigned int)(s_key[t] >> 14));
        s_sc[t] = 1.0f / (1.0f + expf(-logit));
    }
    __syncthreads();

    // ---------------- gather off/shp for cand rows (<=120 loads) ----------------
    if (t < 6 * NMSK) {
        int ci = t / 6, comp = t - ci * 6;
        if (ci < nc) {
            int idx = 16383 - (int)(s_key[ci] & 16383ull);
            size_t base = (size_t)b * 3 * AN;
            const float* src = (comp < 3) ? (off + base + (size_t)comp * AN)
                                          : (shp + base + (size_t)(comp - 3) * AN);
            s_gv[comp][ci] = __ldg(&src[idx]);
        }
    }
    __syncthreads();

    // ---------------- box build ----------------
    if (t < nc) {
        int idx = 16383 - (int)(s_key[t] & 16383ull);
        int z   = idx / 576;
        int rem = idx - z * 576;
        int y   = rem / 24;
        int x   = rem - y * 24;
        float cz = ((float)z + s_gv[0][t]) * 4.0f;   // stride = 96/24 = 4
        float cy = ((float)y + s_gv[1][t]) * 4.0f;
        float cx = ((float)x + s_gv[2][t]) * 4.0f;
        float dz = 2.0f * s_gv[3][t];
        float dy = 2.0f * s_gv[4][t];
        float dx = 2.0f * s_gv[5][t];
        s_ctr[t][0] = cz; s_ctr[t][1] = cy; s_ctr[t][2] = cx;
        s_sz[t][0] = dz;  s_sz[t][1] = dy;  s_sz[t][2] = dx;
        s_lo[t][0] = cz - dz * 0.5f; s_lo[t][1] = cy - dy * 0.5f; s_lo[t][2] = cx - dx * 0.5f;
        s_hi[t][0] = cz + dz * 0.5f; s_hi[t][1] = cy + dy * 0.5f; s_hi[t][2] = cx + dx * 0.5f;
        s_vol[t] = dz * dy * dx;
    }
    __syncthreads();

    // ---------------- IoU bitmask (<=20x20) ----------------
    if (t < nc) {
        float l0 = s_lo[t][0], l1 = s_lo[t][1], l2 = s_lo[t][2];
        float h0 = s_hi[t][0], h1 = s_hi[t][1], h2 = s_hi[t][2];
        float vi = s_vol[t];
        unsigned int m = 0;
        for (int j = 0; j < nc; j++) {
            float iz = fminf(h0, s_hi[j][0]) - fmaxf(l0, s_lo[j][0]);
            float iy = fminf(h1, s_hi[j][1]) - fmaxf(l1, s_lo[j][1]);
            float ix = fminf(h2, s_hi[j][2]) - fmaxf(l2, s_lo[j][2]);
            float inter = fmaxf(iz, 0.0f) * fmaxf(iy, 0.0f) * fmaxf(ix, 0.0f);
            float uni = vi + s_vol[j] - inter;
            float iou = inter / fmaxf(uni, 1e-8f);
            unsigned int hit = (iou > 0.05f) && (j != t);
            m |= hit << j;
        }
        s_m[t] = m;
    }
    __syncthreads();

    // ---------------- serial bitmask NMS ----------------
    if (t == 0) {
        unsigned int supp = 0, kept = 0;
#pragma unroll
        for (int ci = 0; ci < NMSK; ci++) {
            if (ci < nc) {
                unsigned int keep = !((supp >> ci) & 1u);
                kept |= keep << ci;
                if (keep) supp |= s_m[ci];
            }
        }
        s_kept = kept;
    }
    __syncthreads();

    // ---------------- output ----------------
    float* ob = out + (size_t)b * TK * 8;
    if (t < TK) {
        unsigned int kept = s_kept;
        int nk = __popc(kept);
        if (t < nk) {
            int ci = 0, c2 = t;
#pragma unroll
            for (int q = 0; q < NMSK; q++) {
                if ((kept >> q) & 1u) {
                    if (c2 == 0) { ci = q; }
                    c2--;
                }
            }
            float4* o4 = (float4*)(ob + t * 8);
            o4[0] = make_float4(1.0f, s_sc[ci], s_ctr[ci][0], s_ctr[ci][1]);
            o4[1] = make_float4(s_ctr[ci][2], s_sz[ci][0], s_sz[ci][1], s_sz[ci][2]);
        } else {
            float4* o4 = (float4*)(ob + t * 8);
            o4[0] = make_float4(-1.0f, -1.0f, -1.0f, -1.0f);
            o4[1] = make_float4(-1.0f, -1.0f, -1.0f, -1.0f);
        }
    }
}

extern "C" void kernel_launch(void* const* d_in, const int* in_sizes, int n_in,
                              void* d_out, int out_size)
{
    const float* cls = (const float*)d_in[0];
    const float* shp = (const float*)d_in[1];
    const float* off = (const float*)d_in[2];
    float* out = (float*)d_out;
    detect_split_kernel<<<NB * 2, NT>>>(cls, shp, off, out);
}

// round 16
// speedup vs baseline: 1.1631x; 1.1631x over previous
#include <cuda_runtime.h>
#include <cstdint>

#define AN 13824          // 24*24*24 anchors
#define NT 288            // threads per block: 3456/288 = 12 float4 each, no tail
#define NV 3456           // AN/4
#define NL 12             // int4 loads per thread
#define TK 60             // TOPK
#define NMSK 20           // NMS_TOPK
#define SEGSZ 48          // per-warp capacity: mean 18.8, sigma 4.3 -> ~6.8 sigma
#define NWARP 9
#define CAP (SEGSZ * NWARP)   // 432
#define NB 256            // batches
#define THRF 2.25f
#define ITHR 0x40100000   // bits of 2.25f; signed-int compare == float compare (finite)

__device__ __forceinline__ unsigned int fkey(float x) {
    unsigned int b = __float_as_uint(x);
    return (b & 0x80000000u) ? ~b : (b | 0x80000000u);
}
__device__ __forceinline__ float fkey_inv(unsigned int u) {
    unsigned int b = (u & 0x80000000u) ? (u & 0x7fffffffu) : ~u;
    return __uint_as_float(b);
}

__global__ __launch_bounds__(NT, 2)
void detect_fused_kernel(const float* __restrict__ cls,
                         const float* __restrict__ shp,
                         const float* __restrict__ off,
                         float* __restrict__ out)
{
    const int b    = blockIdx.x;
    const int t    = threadIdx.x;
    const int lane = t & 31;
    const int wid  = t >> 5;
    const unsigned int ltmask = (1u << lane) - 1u;

    __shared__ unsigned long long s_seg[NWARP][SEGSZ];
    __shared__ unsigned long long s_cand[CAP];
    __shared__ int   s_segcnt[NWARP], s_segoff[NWARP];
    __shared__ int   s_tot, s_maxseg;
    __shared__ int   s_wcnt[2][NWARP];
    __shared__ int   s_ncand;
    __shared__ unsigned long long s_key[TK];
    __shared__ float s_sc[TK];
    __shared__ unsigned int s_valid[2];
    __shared__ int   s_crow[NMSK];
    __shared__ int   s_nc;
    __shared__ float s_gv[6][NMSK];
    __shared__ float s_ctr[NMSK][3], s_sz[NMSK][3];
    __shared__ float s_lo[NMSK][3], s_hi[NMSK][3], s_vol[NMSK];
    __shared__ unsigned int s_m[NMSK];
    __shared__ unsigned int s_kept;

    // ---------------- Phase 1a: 12 clean int4 loads ----------------
    const int4* cb4 = (const int4*)(cls + (size_t)b * AN);
    int4 v[NL];
#pragma unroll
    for (int j = 0; j < NL; j++)
        v[j] = __ldg(&cb4[t + NT * j]);

    // ---------------- Phase 1b: ballot-segment push (int compare, 1-op fkey) ----------------
    int wcnt = 0;
#define PUSHC(bits, idx) \
    { unsigned int mm = __ballot_sync(0xffffffffu, (bits) >= ITHR); \
      if (mm) { \
        if ((bits) >= ITHR) { \
            int pos = wcnt + __popc(mm & ltmask); \
            if (pos < SEGSZ) \
                s_seg[wid][pos] = \
                    ((unsigned long long)((unsigned int)(bits) | 0x80000000u) << 14) | \
                    (unsigned long long)(16383 - (idx)); \
        } \
        wcnt += __popc(mm); \
      } }
#pragma unroll
    for (int j = 0; j < NL; j++) {
        int base = 4 * (t + NT * j);
        PUSHC(v[j].x, base + 0);
        PUSHC(v[j].y, base + 1);
        PUSHC(v[j].z, base + 2);
        PUSHC(v[j].w, base + 3);
    }
#undef PUSHC

    if (lane == 0) s_segcnt[wid] = wcnt;
    __syncthreads();

    // warp 0: prefix over 9 segment counts
    if (wid == 0) {
        int cnt = (lane < NWARP) ? s_segcnt[lane] : 0;
        int incl = cnt;
#pragma unroll
        for (int o = 1; o < 16; o <<= 1) {
            int vv = __shfl_up_sync(0xffffffffu, incl, o);
            if (lane >= o) incl += vv;
        }
        if (lane < NWARP) s_segoff[lane] = incl - cnt;
        int mx = __reduce_max_sync(0xffffffffu, (lane < NWARP) ? cnt : 0);
        int tt = __shfl_sync(0xffffffffu, incl, NWARP - 1);
        if (lane == 0) { s_tot = tt; s_maxseg = mx; }
    }
    __syncthreads();

    const int tot = s_tot;

    if (tot >= TK && tot <= CAP && s_maxseg <= SEGSZ) {
        // ================= FAST PATH (always taken for N(0,1) data) =================
        {
            int n = (wcnt < SEGSZ) ? wcnt : SEGSZ;
            int base = s_segoff[wid];
            for (int p = lane; p < n; p += 32)
                s_cand[base + p] = s_seg[wid][p];
        }
        __syncthreads();
        // exact ranking -> top-20 keys (all top-60 valid: sigmoid(>=2.25) > 0.15)
        for (int cc2 = t; cc2 < tot; cc2 += NT) {
            unsigned long long k = s_cand[cc2];
            int r = 0;
#pragma unroll 4
            for (int m = 0; m < tot; m++)
                r += (s_cand[m] > k);
            if (r < NMSK) s_key[r] = k;
        }
        if (t == 0) s_nc = NMSK;
        if (t < NMSK) s_crow[t] = t;
        __syncthreads();
        if (t < NMSK) {
            float logit = fkey_inv((unsigned int)(s_key[t] >> 14));
            s_sc[t] = 1.0f / (1.0f + expf(-logit));
        }
        __syncthreads();
    } else {
        // ================= FALLBACK (exact, never taken for this data) =================
        const float* cb = cls + (size_t)b * AN;
        unsigned int T = 0;
        for (int bit = 10; bit >= 0; bit--) {
            unsigned int candT = T | (1u << bit);
            unsigned int Tsh = candT << 21;
            int cc = 0;
            for (int i = t; i < AN; i += NT)
                cc += (fkey(__ldg(&cb[i])) >= Tsh);
            unsigned int ws = __reduce_add_sync(0xffffffffu, (unsigned int)cc);
            int buf = bit & 1;
            if (lane == 0) s_wcnt[buf][wid] = (int)ws;
            __syncthreads();
            int tt = 0;
#pragma unroll
            for (int w = 0; w < NWARP; w++)
                tt += s_wcnt[buf][w];
            if (tt >= TK) T = candT;
            __syncthreads();
        }
        unsigned int cut = T << 21;
        if (cut == 0) cut = 1;
        if (t == 0) s_ncand = 0;
        __syncthreads();
        for (int i = t; i < AN; i += NT) {
            unsigned int k = fkey(__ldg(&cb[i]));
            if (k >= cut) {
                int p = atomicAdd(&s_ncand, 1);
                if (p < CAP)
                    s_cand[p] = ((unsigned long long)k << 14) |
                                (unsigned long long)(16383 - i);
            }
        }
        __syncthreads();
        int C = s_ncand;
        if (C > CAP) C = CAP;
        for (int cc2 = t; cc2 < C; cc2 += NT) {
            unsigned long long k = s_cand[cc2];
            int r = 0;
            for (int m = 0; m < C; m++)
                r += (s_cand[m] > k);
            if (r < TK) s_key[r] = k;
        }
        __syncthreads();
        float sc = 0.0f;
        if (t < TK) {
            float logit = fkey_inv((unsigned int)(s_key[t] >> 14));
            sc = 1.0f / (1.0f + expf(-logit));
            s_sc[t] = sc;
        }
        {
            unsigned int vb = __ballot_sync(0xffffffffu, (t < TK) && (sc > 0.15f));
            if (wid < 2 && lane == 0) s_valid[wid] = vb;
        }
        __syncthreads();
        unsigned long long valid = ((unsigned long long)s_valid[1] << 32) | s_valid[0];
        int nc2 = __popcll(valid);
        if (nc2 > NMSK) nc2 = NMSK;
        if (t == 0) s_nc = nc2;
        if (t < TK) {
            if ((valid >> t) & 1ull) {
                int rv = __popcll(valid & ((1ull << t) - 1ull));
                if (rv < NMSK) s_crow[rv] = t;
            }
        }
        __syncthreads();
    }

    const int nc = s_nc;

    // ---------------- Phase 4: gather off/shp for cand rows (<=120 loads) ----------------
    if (t < 6 * NMSK) {
        int ci = t / 6, comp = t - ci * 6;
        if (ci < nc) {
            int idx = 16383 - (int)(s_key[s_crow[ci]] & 16383ull);
            size_t base = (size_t)b * 3 * AN;
            const float* src = (comp < 3) ? (off + base + (size_t)comp * AN)
                                          : (shp + base + (size_t)(comp - 3) * AN);
            s_gv[comp][ci] = __ldg(&src[idx]);
        }
    }
    __syncthreads();

    // ---------------- Phase 5: box build for cand rows ----------------
    if (t < nc) {
        int idx = 16383 - (int)(s_key[s_crow[t]] & 16383ull);
        int z   = idx / 576;
        int rem = idx - z * 576;
        int y   = rem / 24;
        int x   = rem - y * 24;
        float cz = ((float)z + s_gv[0][t]) * 4.0f;   // stride = 96/24 = 4
        float cy = ((float)y + s_gv[1][t]) * 4.0f;
        float cx = ((float)x + s_gv[2][t]) * 4.0f;
        float dz = 2.0f * s_gv[3][t];
        float dy = 2.0f * s_gv[4][t];
        float dx = 2.0f * s_gv[5][t];
        s_ctr[t][0] = cz; s_ctr[t][1] = cy; s_ctr[t][2] = cx;
        s_sz[t][0] = dz;  s_sz[t][1] = dy;  s_sz[t][2] = dx;
        s_lo[t][0] = cz - dz * 0.5f; s_lo[t][1] = cy - dy * 0.5f; s_lo[t][2] = cx - dx * 0.5f;
        s_hi[t][0] = cz + dz * 0.5f; s_hi[t][1] = cy + dy * 0.5f; s_hi[t][2] = cx + dx * 0.5f;
        s_vol[t] = dz * dy * dx;
    }
    __syncthreads();

    // ---------------- Phase 6: IoU bitmask among cand rows (<=20x20) ----------------
    if (t < nc) {
        float l0 = s_lo[t][0], l1 = s_lo[t][1], l2 = s_lo[t][2];
        float h0 = s_hi[t][0], h1 = s_hi[t][1], h2 = s_hi[t][2];
        float vi = s_vol[t];
        unsigned int m = 0;
        for (int j = 0; j < nc; j++) {
            float iz = fminf(h0, s_hi[j][0]) - fmaxf(l0, s_lo[j][0]);
            float iy = fminf(h1, s_hi[j][1]) - fmaxf(l1, s_lo[j][1]);
            float ix = fminf(h2, s_hi[j][2]) - fmaxf(l2, s_lo[j][2]);
            float inter = fmaxf(iz, 0.0f) * fmaxf(iy, 0.0f) * fmaxf(ix, 0.0f);
            float uni = vi + s_vol[j] - inter;
            float iou = inter / fmaxf(uni, 1e-8f);
            unsigned int hit = (iou > 0.05f) && (j != t);
            m |= hit << j;
        }
        s_m[t] = m;
    }
    __syncthreads();

    // ---------------- Phase 7: serial bitmask NMS ----------------
    if (t == 0) {
        unsigned int supp = 0, kept = 0;
#pragma unroll
        for (int ci = 0; ci < NMSK; ci++) {
            if (ci < nc) {
                unsigned int keep = !((supp >> ci) & 1u);
                kept |= keep << ci;
                if (keep) supp |= s_m[ci];
            }
        }
        s_kept = kept;
    }
    __syncthreads();

    // ---------------- Phase 8: output (kept in rank order, -1 padding) ----------------
    float* ob = out + (size_t)b * TK * 8;
    if (t < TK) {
        unsigned int kept = s_kept;
        int nk = __popc(kept);
        if (t < nk) {
            int ci = 0, c2 = t;
#pragma unroll
            for (int q = 0; q < NMSK; q++) {
                if ((kept >> q) & 1u) {
                    if (c2 == 0) { ci = q; }
                    c2--;
                }
            }
            float4* o4 = (float4*)(ob + t * 8);
            o4[0] = make_float4(1.0f, s_sc[s_crow[ci]], s_ctr[ci][0], s_ctr[ci][1]);
            o4[1] = make_float4(s_ctr[ci][2], s_sz[ci][0], s_sz[ci][1], s_sz[ci][2]);
        } else {
            float4* o4 = (float4*)(ob + t * 8);
            o4[0] = make_float4(-1.0f, -1.0f, -1.0f, -1.0f);
            o4[1] = make_float4(-1.0f, -1.0f, -1.0f, -1.0f);
        }
    }
}

extern "C" void kernel_launch(void* const* d_in, const int* in_sizes, int n_in,
                              void* d_out, int out_size)
{
    const float* cls = (const float*)d_in[0];
    const float* shp = (const float*)d_in[1];
    const float* off = (const float*)d_in[2];
    float* out = (float*)d_out;
    detect_fused_kernel<<<NB, NT>>>(cls, shp, off, out);
}